// round 5
// baseline (speedup 1.0000x reference)
#include <cuda_runtime.h>
#include <cstdint>

// Fused 3-stage Tucker transform using legacy mma.sync tf32 tensor cores
// (compute_100 baseline — tcgen05 is unavailable under this toolchain target).
//
// Per CTA = one batch tile of 32*32*32 fp32 kept in smem.
// Stage GEMM: out[m,i] = sum_c A[m,c] * w[c,i], M=1024, N=32, K=32.
// tf32 two-plane split: v = t0 + t1; product = t0*B0 + t0*B1 + t1*B0 (drop t1*B1).
// Smem column swizzle scol(r,c) = (c + 4r + (r>>5)) & 31 makes both the
// A-fragment reads and the transposed epilogue stores bank-conflict-free.

#define NT 512
#define S_ELEMS 32768                 // 1024 rows x 32 cols fp32
#define WSTRIDE 40                    // weight-plane row stride (bank-distinct B frags)
#define WPLANE  (32 * WSTRIDE)        // u32 per plane
#define SMEM_BYTES ((S_ELEMS + 6 * WPLANE) * 4)   // 131072 + 30720 = 161792

__device__ __forceinline__ uint32_t f2tf(float f) {
    uint32_t u;
    asm("cvt.rna.tf32.f32 %0, %1;" : "=r"(u) : "f"(f));
    return u;
}

__device__ __forceinline__ int scol(int r, int c) {
    return (c + 4 * r + (r >> 5)) & 31;
}

__device__ __forceinline__ void mma8(float* d, const uint32_t* a, uint32_t b0, uint32_t b1) {
    asm volatile(
        "mma.sync.aligned.m16n8k8.row.col.f32.tf32.tf32.f32 "
        "{%0,%1,%2,%3}, {%4,%5,%6,%7}, {%8,%9}, {%0,%1,%2,%3};"
        : "+f"(d[0]), "+f"(d[1]), "+f"(d[2]), "+f"(d[3])
        : "r"(a[0]), "r"(a[1]), "r"(a[2]), "r"(a[3]), "r"(b0), "r"(b1));
}

__global__ __launch_bounds__(NT, 1)
void tucker3_mma(const float* __restrict__ x,
                 const float* __restrict__ w0,
                 const float* __restrict__ w1,
                 const float* __restrict__ w2,
                 float* __restrict__ out)
{
    extern __shared__ float smem[];
    float* S = smem;
    uint32_t* Wp = (uint32_t*)(smem + S_ELEMS);   // [stage*2+plane][k*WSTRIDE + n]

    const int tid  = threadIdx.x;
    const int wid  = tid >> 5;
    const int lane = tid & 31;
    const int g    = lane >> 2;    // groupID (0..7)
    const int tig  = lane & 3;     // thread-in-group (0..3)
    const long base = (long)blockIdx.x << 15;

    // ---- Weight prep: split each w into two tf32 planes. ----
    {
        const float* ws[3] = {w0, w1, w2};
        #pragma unroll
        for (int s = 0; s < 3; s++) {
            for (int e = tid; e < 1024; e += NT) {
                int c = e >> 5, i = e & 31;
                int o = c * WSTRIDE + i;
                float v = ws[s][e];
                uint32_t u0 = f2tf(v);
                uint32_t u1 = f2tf(v - __uint_as_float(u0));
                Wp[(2 * s + 0) * WPLANE + o] = u0;
                Wp[(2 * s + 1) * WPLANE + o] = u1;
            }
        }
    }

    // ---- Stage-0 fill: A[m][c] = x[c*1024 + m], coalesced reads. ----
    {
        const float* xb = x + base;
        #pragma unroll 4
        for (int j = 0; j < 64; j++) {
            int e = j * NT + tid;
            float v = xb[e];
            int m = e & 1023, c = e >> 10;
            S[m * 32 + scol(m, c)] = v;
        }
    }
    __syncthreads();

    const int mWarp = wid * 64;

    #pragma unroll 1
    for (int s = 0; s < 3; s++) {
        const uint32_t* W0 = Wp + (2 * s) * WPLANE;
        const uint32_t* W1 = W0 + WPLANE;

        float acc[4][4][4];
        #pragma unroll
        for (int a = 0; a < 4; a++)
            #pragma unroll
            for (int b = 0; b < 4; b++)
                #pragma unroll
                for (int q = 0; q < 4; q++)
                    acc[a][b][q] = 0.0f;

        // Strip pairs share B-fragment loads.
        #pragma unroll
        for (int sp = 0; sp < 2; sp++) {
            #pragma unroll
            for (int ks = 0; ks < 4; ks++) {
                const int kb = ks * 8 + tig;
                uint32_t bp0[4], bp1[4], bq0[4], bq1[4];
                #pragma unroll
                for (int nt = 0; nt < 4; nt++) {
                    int n = nt * 8 + g;
                    bp0[nt] = W0[kb * WSTRIDE + n];
                    bp1[nt] = W0[(kb + 4) * WSTRIDE + n];
                    bq0[nt] = W1[kb * WSTRIDE + n];
                    bq1[nt] = W1[(kb + 4) * WSTRIDE + n];
                }
                #pragma unroll
                for (int st2 = 0; st2 < 2; st2++) {
                    const int sidx = sp * 2 + st2;
                    const int mS = mWarp + sidx * 16;
                    const int r0 = mS + g, r1 = r0 + 8;
                    const int c0 = ks * 8 + tig, c1 = c0 + 4;

                    float af0 = S[r0 * 32 + scol(r0, c0)];
                    float af1 = S[r1 * 32 + scol(r1, c0)];
                    float af2 = S[r0 * 32 + scol(r0, c1)];
                    float af3 = S[r1 * 32 + scol(r1, c1)];

                    uint32_t ua[4], va[4];
                    ua[0] = f2tf(af0); va[0] = f2tf(af0 - __uint_as_float(ua[0]));
                    ua[1] = f2tf(af1); va[1] = f2tf(af1 - __uint_as_float(ua[1]));
                    ua[2] = f2tf(af2); va[2] = f2tf(af2 - __uint_as_float(ua[2]));
                    ua[3] = f2tf(af3); va[3] = f2tf(af3 - __uint_as_float(ua[3]));

                    #pragma unroll
                    for (int nt = 0; nt < 4; nt++) {
                        mma8(acc[sidx][nt], ua, bp0[nt], bp1[nt]);   // t0 * B0
                        mma8(acc[sidx][nt], ua, bq0[nt], bq1[nt]);   // t0 * B1
                        mma8(acc[sidx][nt], va, bp0[nt], bp1[nt]);   // t1 * B0
                    }
                }
            }
        }

        __syncthreads();   // all reads of S complete before transposed writes

        if (s < 2) {
            // out[m][i] -> next-stage A[r'][c'], r' = (m&31)*32 + i, c' = m>>5.
            #pragma unroll
            for (int st = 0; st < 4; st++) {
                const int mS = mWarp + st * 16;
                const int m0 = mS + g, m1 = m0 + 8;
                const int cA = mS >> 5;
                #pragma unroll
                for (int nt = 0; nt < 4; nt++) {
                    const int i0 = nt * 8 + 2 * tig;
                    const int r0p = (m0 & 31) * 32 + i0;
                    const int r1p = (m1 & 31) * 32 + i0;
                    S[r0p * 32 + scol(r0p, cA)]           = acc[st][nt][0];
                    S[(r0p + 1) * 32 + scol(r0p + 1, cA)] = acc[st][nt][1];
                    S[r1p * 32 + scol(r1p, cA)]           = acc[st][nt][2];
                    S[(r1p + 1) * 32 + scol(r1p + 1, cA)] = acc[st][nt][3];
                }
            }
            __syncthreads();
        } else {
            // Final stage: write straight to gmem, out flat = m*32 + i.
            float* ob = out + base;
            #pragma unroll
            for (int st = 0; st < 4; st++) {
                const int mS = mWarp + st * 16;
                const int m0 = mS + g, m1 = m0 + 8;
                #pragma unroll
                for (int nt = 0; nt < 4; nt++) {
                    const int i0 = nt * 8 + 2 * tig;
                    *(float2*)&ob[m0 * 32 + i0] = make_float2(acc[st][nt][0], acc[st][nt][1]);
                    *(float2*)&ob[m1 * 32 + i0] = make_float2(acc[st][nt][2], acc[st][nt][3]);
                }
            }
        }
    }
}

extern "C" void kernel_launch(void* const* d_in, const int* in_sizes, int n_in,
                              void* d_out, int out_size)
{
    const float* x  = (const float*)d_in[0];
    const float* w0 = (const float*)d_in[1];
    const float* w1 = (const float*)d_in[2];
    const float* w2 = (const float*)d_in[3];
    float* out = (float*)d_out;

    const int nBatch = in_sizes[0] >> 15;

    cudaFuncSetAttribute(tucker3_mma,
                         cudaFuncAttributeMaxDynamicSharedMemorySize, SMEM_BYTES);
    tucker3_mma<<<nBatch, NT, SMEM_BYTES>>>(x, w0, w1, w2, out);
}

// round 6
// speedup vs baseline: 1.1663x; 1.1663x over previous
#include <cuda_runtime.h>
#include <cstdint>

// Fused 3-stage Tucker transform using mma.sync tf32 tensor cores.
// Round 6: 1024 threads/CTA (2x occupancy), B-load hoist, accumulator-
// interleaved split passes.
//
// Per CTA = one batch tile of 32*32*32 fp32 kept in smem.
// Stage GEMM: out[m,i] = sum_c A[m,c] * w[c,i], M=1024, N=32, K=32.
// tf32 two-plane split: v = t0 + t1; product = t0*B0 + t0*B1 + t1*B0.
// Smem column swizzle scol(r,c) = (c + 4r + (r>>5)) & 31: A-fragment reads,
// epilogue transposed stores, and B reads are all bank-conflict-free.

#define NT 1024
#define S_ELEMS 32768                 // 1024 rows x 32 cols fp32
#define WSTRIDE 40                    // weight-plane row stride
#define WPLANE  (32 * WSTRIDE)
#define SMEM_BYTES ((S_ELEMS + 6 * WPLANE) * 4)   // 161792

__device__ __forceinline__ uint32_t f2tf(float f) {
    uint32_t u;
    asm("cvt.rna.tf32.f32 %0, %1;" : "=r"(u) : "f"(f));
    return u;
}

__device__ __forceinline__ int scol(int r, int c) {
    return (c + 4 * r + (r >> 5)) & 31;
}

__device__ __forceinline__ void mma8(float* d, const uint32_t* a, uint32_t b0, uint32_t b1) {
    asm volatile(
        "mma.sync.aligned.m16n8k8.row.col.f32.tf32.tf32.f32 "
        "{%0,%1,%2,%3}, {%4,%5,%6,%7}, {%8,%9}, {%0,%1,%2,%3};"
        : "+f"(d[0]), "+f"(d[1]), "+f"(d[2]), "+f"(d[3])
        : "r"(a[0]), "r"(a[1]), "r"(a[2]), "r"(a[3]), "r"(b0), "r"(b1));
}

__global__ __launch_bounds__(NT, 1)
void tucker3_mma(const float* __restrict__ x,
                 const float* __restrict__ w0,
                 const float* __restrict__ w1,
                 const float* __restrict__ w2,
                 float* __restrict__ out)
{
    extern __shared__ float smem[];
    float* S = smem;
    uint32_t* Wp = (uint32_t*)(smem + S_ELEMS);   // [stage*2+plane][k*WSTRIDE + n]

    const int tid  = threadIdx.x;
    const int wid  = tid >> 5;
    const int lane = tid & 31;
    const int g    = lane >> 2;    // groupID (0..7)
    const int tig  = lane & 3;     // thread-in-group (0..3)
    const long base = (long)blockIdx.x << 15;

    // ---- Weight prep: split each w into two tf32 planes. ----
    if (tid < 1024) {
        int e = tid;
        int c = e >> 5, i = e & 31;
        int o = c * WSTRIDE + i;
        float v0 = w0[e], v1 = w1[e], v2 = w2[e];
        uint32_t u;
        u = f2tf(v0);
        Wp[0 * WPLANE + o] = u;
        Wp[1 * WPLANE + o] = f2tf(v0 - __uint_as_float(u));
        u = f2tf(v1);
        Wp[2 * WPLANE + o] = u;
        Wp[3 * WPLANE + o] = f2tf(v1 - __uint_as_float(u));
        u = f2tf(v2);
        Wp[4 * WPLANE + o] = u;
        Wp[5 * WPLANE + o] = f2tf(v2 - __uint_as_float(u));
    }

    // ---- Stage-0 fill: A[m][c] = x[c*1024 + m], coalesced reads. ----
    {
        const float* xb = x + base;
        #pragma unroll 4
        for (int j = 0; j < 32; j++) {
            float v = xb[j * NT + tid];
            int m = tid, c = j;                 // NT == 1024
            S[m * 32 + scol(m, c)] = v;
        }
    }
    __syncthreads();

    const int mWarp = wid * 32;                 // 32 rows per warp, 2 strips

    #pragma unroll 1
    for (int s = 0; s < 3; s++) {
        const uint32_t* W0 = Wp + (2 * s) * WPLANE;
        const uint32_t* W1 = W0 + WPLANE;

        float acc[2][4][4];
        #pragma unroll
        for (int a = 0; a < 2; a++)
            #pragma unroll
            for (int b = 0; b < 4; b++)
                #pragma unroll
                for (int q = 0; q < 4; q++)
                    acc[a][b][q] = 0.0f;

        #pragma unroll
        for (int ks = 0; ks < 4; ks++) {
            const int kb = ks * 8 + tig;
            uint32_t bp0[4], bp1[4], bq0[4], bq1[4];
            #pragma unroll
            for (int nt = 0; nt < 4; nt++) {
                int n = nt * 8 + g;
                bp0[nt] = W0[kb * WSTRIDE + n];
                bp1[nt] = W0[(kb + 4) * WSTRIDE + n];
                bq0[nt] = W1[kb * WSTRIDE + n];
                bq1[nt] = W1[(kb + 4) * WSTRIDE + n];
            }
            #pragma unroll
            for (int st = 0; st < 2; st++) {
                const int mS = mWarp + st * 16;
                const int r0 = mS + g, r1 = r0 + 8;
                const int c0 = ks * 8 + tig, c1 = c0 + 4;

                float af0 = S[r0 * 32 + scol(r0, c0)];
                float af1 = S[r1 * 32 + scol(r1, c0)];
                float af2 = S[r0 * 32 + scol(r0, c1)];
                float af3 = S[r1 * 32 + scol(r1, c1)];

                uint32_t ua[4], va[4];
                ua[0] = f2tf(af0); va[0] = f2tf(af0 - __uint_as_float(ua[0]));
                ua[1] = f2tf(af1); va[1] = f2tf(af1 - __uint_as_float(ua[1]));
                ua[2] = f2tf(af2); va[2] = f2tf(af2 - __uint_as_float(ua[2]));
                ua[3] = f2tf(af3); va[3] = f2tf(af3 - __uint_as_float(ua[3]));

                // Interleave split terms across independent nt accumulators:
                // consecutive MMAs never share a destination (no RAW chain).
                #pragma unroll
                for (int nt = 0; nt < 4; nt++) mma8(acc[st][nt], ua, bp0[nt], bp1[nt]);
                #pragma unroll
                for (int nt = 0; nt < 4; nt++) mma8(acc[st][nt], ua, bq0[nt], bq1[nt]);
                #pragma unroll
                for (int nt = 0; nt < 4; nt++) mma8(acc[st][nt], va, bp0[nt], bp1[nt]);
            }
        }

        __syncthreads();   // all reads of S complete before transposed writes

        if (s < 2) {
            // out[m][i] -> next-stage A[r'][c'], r' = (m&31)*32 + i, c' = m>>5.
            #pragma unroll
            for (int st = 0; st < 2; st++) {
                const int mS = mWarp + st * 16;
                const int m0 = mS + g, m1 = m0 + 8;
                const int cA = mS >> 5;
                #pragma unroll
                for (int nt = 0; nt < 4; nt++) {
                    const int i0 = nt * 8 + 2 * tig;
                    const int r0p = (m0 & 31) * 32 + i0;
                    const int r1p = (m1 & 31) * 32 + i0;
                    S[r0p * 32 + scol(r0p, cA)]           = acc[st][nt][0];
                    S[(r0p + 1) * 32 + scol(r0p + 1, cA)] = acc[st][nt][1];
                    S[r1p * 32 + scol(r1p, cA)]           = acc[st][nt][2];
                    S[(r1p + 1) * 32 + scol(r1p + 1, cA)] = acc[st][nt][3];
                }
            }
            __syncthreads();
        } else {
            // Final stage: write straight to gmem, out flat = m*32 + i.
            float* ob = out + base;
            #pragma unroll
            for (int st = 0; st < 2; st++) {
                const int mS = mWarp + st * 16;
                const int m0 = mS + g, m1 = m0 + 8;
                #pragma unroll
                for (int nt = 0; nt < 4; nt++) {
                    const int i0 = nt * 8 + 2 * tig;
                    *(float2*)&ob[m0 * 32 + i0] = make_float2(acc[st][nt][0], acc[st][nt][1]);
                    *(float2*)&ob[m1 * 32 + i0] = make_float2(acc[st][nt][2], acc[st][nt][3]);
                }
            }
        }
    }
}

extern "C" void kernel_launch(void* const* d_in, const int* in_sizes, int n_in,
                              void* d_out, int out_size)
{
    const float* x  = (const float*)d_in[0];
    const float* w0 = (const float*)d_in[1];
    const float* w1 = (const float*)d_in[2];
    const float* w2 = (const float*)d_in[3];
    float* out = (float*)d_out;

    const int nBatch = in_sizes[0] >> 15;

    cudaFuncSetAttribute(tucker3_mma,
                         cudaFuncAttributeMaxDynamicSharedMemorySize, SMEM_BYTES);
    tucker3_mma<<<nBatch, NT, SMEM_BYTES>>>(x, w0, w1, w2, out);
}